// round 15
// baseline (speedup 1.0000x reference)
#include <cuda_runtime.h>
#include <cuda_fp16.h>
#include <math.h>
#include <stdint.h>

#define B_SZ   4
#define L_SEQ  2048
#define E_DIM  2048
#define NH     16
#define HD     128
#define M_TOTAL (B_SZ * L_SEQ)   /* 8192 */
#define K_DIM   E_DIM            /* 2048 */
#define N_TOTAL (3 * E_DIM)      /* 6144 */
#define BH     (B_SZ * NH)       /* 64 */

// Scratch: fp16 x, W; split q/k/v head-major buffers [bh][L][HD].
__device__ __half g_xh[(size_t)M_TOTAL * (size_t)K_DIM];
__device__ __half g_wh[(size_t)N_TOTAL * (size_t)K_DIM];
__device__ __half g_qh[(size_t)BH * L_SEQ * HD];
__device__ __half g_kh[(size_t)BH * L_SEQ * HD];
__device__ __half g_vh[(size_t)BH * L_SEQ * HD];

// ---------------------------------------------------------------------------
__device__ __forceinline__ uint32_t smem_u32(const void* p) {
    uint32_t a;
    asm("{ .reg .u64 t; cvta.to.shared.u64 t, %1; cvt.u32.u64 %0, t; }"
        : "=r"(a) : "l"(p));
    return a;
}
__device__ __forceinline__ uint32_t packh2(float a, float b) {
    __half2 h = __floats2half2_rn(a, b);
    return *(uint32_t*)&h;
}

#define MMA_F16(c, a0, a1, a2, a3, b0, b1)                                    \
    asm volatile(                                                             \
        "mma.sync.aligned.m16n8k16.row.col.f32.f16.f16.f32 "                  \
        "{%0,%1,%2,%3}, {%4,%5,%6,%7}, {%8,%9}, {%0,%1,%2,%3};"               \
        : "+f"((c)[0]), "+f"((c)[1]), "+f"((c)[2]), "+f"((c)[3])              \
        : "r"(a0), "r"(a1), "r"(a2), "r"(a3), "r"(b0), "r"(b1))

#define LDSM_X4(r0, r1, r2, r3, addr)                                         \
    asm volatile("ldmatrix.sync.aligned.m8n8.x4.shared.b16 "                  \
                 "{%0,%1,%2,%3}, [%4];"                                       \
                 : "=r"(r0), "=r"(r1), "=r"(r2), "=r"(r3) : "r"(addr))

#define LDSM_X4_T(r0, r1, r2, r3, addr)                                       \
    asm volatile("ldmatrix.sync.aligned.m8n8.x4.trans.shared.b16 "            \
                 "{%0,%1,%2,%3}, [%4];"                                       \
                 : "=r"(r0), "=r"(r1), "=r"(r2), "=r"(r3) : "r"(addr))

#define CP_ASYNC16(dst, src)                                                  \
    asm volatile("cp.async.cg.shared.global [%0], [%1], 16;"                  \
                 :: "r"(dst), "l"(src))
#define CP_COMMIT() asm volatile("cp.async.commit_group;" ::: "memory")
#define CP_WAIT(n)  asm volatile("cp.async.wait_group %0;" :: "n"(n) : "memory")

// ===========================================================================
// Kernel 0: fp32 -> fp16 conversion
// ===========================================================================
__global__ __launch_bounds__(256) void to_half_kernel(
    const float* __restrict__ src, __half* __restrict__ dst, int n4)
{
    int i = blockIdx.x * blockDim.x + threadIdx.x;
    if (i >= n4) return;
    float4 v = ((const float4*)src)[i];
    __half2 h0 = __floats2half2_rn(v.x, v.y);
    __half2 h1 = __floats2half2_rn(v.z, v.w);
    ((uint2*)dst)[i] = make_uint2(*(uint32_t*)&h0, *(uint32_t*)&h1);
}

// ===========================================================================
// Kernel 1: QKV GEMM for ONE batch (R11 config). CTA 128x128, BK=64 halves,
// 3-stage cp.async, 8 warps 4(M)x2(N), 2 CTAs/SM. Grid (48, 16).
// Fused bias + L2-norm epilogue -> head-major g_qh/g_kh/g_vh (fp16).
// ===========================================================================
#define GSTR 72
#define G_STAGE_H (2 * 128 * GSTR)
#define G_SMEM_BYTES (3 * G_STAGE_H * 2)   /* 110592 B */

__global__ __launch_bounds__(256, 2) void qkv_gemm_b(
    int bb, const float* __restrict__ bias)
{
    extern __shared__ __align__(16) __half gsh[];
    const uint32_t sbase = smem_u32(gsh);
    float* red = (float*)gsh;

    const int tid  = threadIdx.x;
    const int lane = tid & 31;
    const int wid  = tid >> 5;
    const int gid  = lane >> 2;
    const int tig  = lane & 3;
    const int wm   = wid & 3;
    const int wn   = wid >> 2;
    const int mt   = blockIdx.y;                 // 0..15 within batch
    const int m0   = bb * L_SEQ + mt * 128;
    const int n0   = blockIdx.x * 128;

    const uint32_t a_lm = (uint32_t)(((lane & 15) * GSTR + (lane >> 4) * 8) * 2);
    const uint32_t b_lm = (uint32_t)(((((lane & 7) + ((lane >> 4) & 1) * 8) * GSTR)
                                      + ((lane >> 3) & 1) * 8) * 2);
    const int cp_r = tid >> 3;
    const int cp_c = tid & 7;

    float C[2][8][4];
#pragma unroll
    for (int t = 0; t < 2; t++)
#pragma unroll
        for (int u = 0; u < 8; u++)
#pragma unroll
            for (int j = 0; j < 4; j++) C[t][u][j] = 0.f;

    const int NIT = K_DIM / 64;

    auto stage_load = [&](int it, int st) {
        const int k0 = it * 64;
        const uint32_t sb = sbase + (uint32_t)(st * G_STAGE_H * 2);
#pragma unroll
        for (int i = 0; i < 4; i++) {
            int r = i * 32 + cp_r;
            uint32_t dst = sb + (uint32_t)((r * GSTR + cp_c * 8) * 2);
            const __half* src = g_xh + (size_t)(m0 + r) * K_DIM + k0 + cp_c * 8;
            CP_ASYNC16(dst, src);
        }
#pragma unroll
        for (int i = 0; i < 4; i++) {
            int r = i * 32 + cp_r;
            uint32_t dst = sb + (uint32_t)(((128 + r) * GSTR + cp_c * 8) * 2);
            const __half* src = g_wh + (size_t)(n0 + r) * K_DIM + k0 + cp_c * 8;
            CP_ASYNC16(dst, src);
        }
    };

    stage_load(0, 0); CP_COMMIT();
    stage_load(1, 1); CP_COMMIT();

    for (int it = 0; it < NIT; ++it) {
        CP_WAIT(1);
        __syncthreads();
        if (it + 2 < NIT) stage_load(it + 2, (it + 2) % 3);
        CP_COMMIT();

        const uint32_t sb = sbase + (uint32_t)(((it % 3) * G_STAGE_H) * 2);
        const uint32_t aB = sb + (uint32_t)(wm * 32 * GSTR * 2) + a_lm;
        const uint32_t bB = sb + (uint32_t)((128 + wn * 64) * GSTR * 2) + b_lm;

#pragma unroll
        for (int s = 0; s < 4; s++) {
            uint32_t a0[4], a1[4];
            LDSM_X4(a0[0], a0[1], a0[2], a0[3], aB + s * 32);
            LDSM_X4(a1[0], a1[1], a1[2], a1[3], aB + 16 * GSTR * 2 + s * 32);
#pragma unroll
            for (int up = 0; up < 4; up++) {
                uint32_t b[4];
                LDSM_X4(b[0], b[1], b[2], b[3],
                        bB + up * 16 * GSTR * 2 + s * 32);
                MMA_F16(C[0][up * 2],     a0[0], a0[1], a0[2], a0[3], b[0], b[1]);
                MMA_F16(C[0][up * 2 + 1], a0[0], a0[1], a0[2], a0[3], b[2], b[3]);
                MMA_F16(C[1][up * 2],     a1[0], a1[1], a1[2], a1[3], b[0], b[1]);
                MMA_F16(C[1][up * 2 + 1], a1[0], a1[1], a1[2], a1[3], b[2], b[3]);
            }
        }
    }

    // ---------------- fused epilogue ----------------
    CP_WAIT(0);
    __syncthreads();
    const int head = blockIdx.x / 3;
    const int comp = blockIdx.x % 3;
    const int bh   = bb * NH + head;
    __half* dstbuf = (comp == 0) ? g_qh : (comp == 1) ? g_kh : g_vh;

#pragma unroll
    for (int t = 0; t < 2; t++)
#pragma unroll
        for (int u = 0; u < 8; u++) {
            int col = n0 + wn * 64 + u * 8 + tig * 2;
            float2 bv = *(const float2*)&bias[col];
            C[t][u][0] += bv.x; C[t][u][1] += bv.y;
            C[t][u][2] += bv.x; C[t][u][3] += bv.y;
        }

    float sc[2][2] = {{1.f, 1.f}, {1.f, 1.f}};
    if (comp < 2) {
#pragma unroll
        for (int t = 0; t < 2; t++)
#pragma unroll
            for (int hh = 0; hh < 2; hh++) {
                float p = 0.f;
#pragma unroll
                for (int u = 0; u < 8; u++)
                    p += C[t][u][2 * hh] * C[t][u][2 * hh]
                       + C[t][u][2 * hh + 1] * C[t][u][2 * hh + 1];
                p += __shfl_xor_sync(0xffffffffu, p, 1);
                p += __shfl_xor_sync(0xffffffffu, p, 2);
                if (tig == 0)
                    red[(wm * 32 + t * 16 + hh * 8 + gid) * 2 + wn] = p;
            }
        __syncthreads();
#pragma unroll
        for (int t = 0; t < 2; t++)
#pragma unroll
            for (int hh = 0; hh < 2; hh++) {
                int r = wm * 32 + t * 16 + hh * 8 + gid;
                float s = red[r * 2] + red[r * 2 + 1];
                sc[t][hh] = 1.0f / fmaxf(sqrtf(s), 1e-12f);
            }
    }

#pragma unroll
    for (int t = 0; t < 2; t++) {
        int r0 = wm * 32 + t * 16 + gid;
        int l0 = mt * 128 + r0;
#pragma unroll
        for (int u = 0; u < 8; u++) {
            int chd = wn * 64 + u * 8 + tig * 2;
            __half2 h0 = __floats2half2_rn(C[t][u][0] * sc[t][0],
                                           C[t][u][1] * sc[t][0]);
            __half2 h1 = __floats2half2_rn(C[t][u][2] * sc[t][1],
                                           C[t][u][3] * sc[t][1]);
            *(__half2*)&dstbuf[((size_t)bh * L_SEQ + l0) * HD + chd]     = h0;
            *(__half2*)&dstbuf[((size_t)bh * L_SEQ + l0 + 8) * HD + chd] = h1;
        }
    }
}

// ===========================================================================
// Kernel 2: attention for ONE batch (R11 config). BM=128, 4 warps x 32 rows,
// 2 CTAs/SM; P in registers; exp via MUFU. Grid (16, 16).
// ===========================================================================
#define A_KSTR 136
#define A_KOFF(buf) ((buf) * (64 * A_KSTR))
#define A_VOFF(buf) (2 * 64 * A_KSTR + (buf) * (64 * A_KSTR))
#define A_SMEM_BYTES (4 * 64 * A_KSTR * 2)   /* 69632 B */

__global__ __launch_bounds__(128, 2) void attn_b(
    int bb, float* __restrict__ out)
{
    extern __shared__ __align__(16) __half smh[];
    const uint32_t sbase = smem_u32(smh);

    const int tid  = threadIdx.x;
    const int lane = tid & 31;
    const int wid  = tid >> 5;
    const int gid  = lane >> 2;
    const int tig  = lane & 3;
    const int base = wid * 32;
    const int m0   = blockIdx.x * 128;
    const int h    = blockIdx.y;
    const int bh   = bb * NH + h;
    const __half* qrow = g_qh + (size_t)bh * L_SEQ * HD;
    const __half* krow = g_kh + (size_t)bh * L_SEQ * HD;
    const __half* vrow = g_vh + (size_t)bh * L_SEQ * HD;

    uint32_t Qf[2][8][4];
#pragma unroll
    for (int rg = 0; rg < 2; rg++) {
        const __half* rq  = qrow + (size_t)(m0 + base + rg * 16 + gid) * HD;
        const __half* rq8 = rq + (size_t)8 * HD;
#pragma unroll
        for (int s = 0; s < 8; s++) {
            int c = s * 16 + tig * 2;
            Qf[rg][s][0] = *(const uint32_t*)&rq [c];
            Qf[rg][s][1] = *(const uint32_t*)&rq8[c];
            Qf[rg][s][2] = *(const uint32_t*)&rq [c + 8];
            Qf[rg][s][3] = *(const uint32_t*)&rq8[c + 8];
        }
    }

    const uint32_t k_lm = (uint32_t)(((((lane & 7) + ((lane >> 4) & 1) * 8) * A_KSTR)
                                      + ((lane >> 3) & 1) * 8) * 2);
    const uint32_t v_lm = (uint32_t)(((((lane & 7) + ((lane >> 3) & 1) * 8) * A_KSTR)
                                      + (lane >> 4) * 8) * 2);

    const int cp_r = tid >> 4;    // 0..7
    const int cp_c = tid & 15;    // 0..15

    auto stage_load = [&](int tt, int buf) {
        const int n0t = tt * 64;
#pragma unroll
        for (int i = 0; i < 8; i++) {
            int r = i * 8 + cp_r;
            uint32_t dst = sbase + (uint32_t)((A_KOFF(buf) + r * A_KSTR + cp_c * 8) * 2);
            CP_ASYNC16(dst, krow + (size_t)(n0t + r) * HD + cp_c * 8);
        }
#pragma unroll
        for (int i = 0; i < 8; i++) {
            int r = i * 8 + cp_r;
            uint32_t dst = sbase + (uint32_t)((A_VOFF(buf) + r * A_KSTR + cp_c * 8) * 2);
            CP_ASYNC16(dst, vrow + (size_t)(n0t + r) * HD + cp_c * 8);
        }
    };

    float O[2][16][4];
#pragma unroll
    for (int rg = 0; rg < 2; rg++)
#pragma unroll
        for (int u = 0; u < 16; u++)
#pragma unroll
            for (int j = 0; j < 4; j++) O[rg][u][j] = 0.f;
    float lr[2][2] = {{0.f, 0.f}, {0.f, 0.f}};

    stage_load(0, 0); CP_COMMIT();

    for (int tt = 0; tt < L_SEQ / 64; ++tt) {
        CP_WAIT(0);
        __syncthreads();
        if (tt + 1 < L_SEQ / 64) stage_load(tt + 1, (tt + 1) & 1);
        CP_COMMIT();

        const int buf = tt & 1;
        const uint32_t kB = sbase + (uint32_t)(A_KOFF(buf) * 2) + k_lm;
        const uint32_t vB = sbase + (uint32_t)(A_VOFF(buf) * 2) + v_lm;

#pragma unroll
        for (int c = 0; c < 2; c++) {
            float S[2][4][4];
#pragma unroll
            for (int rg = 0; rg < 2; rg++)
#pragma unroll
                for (int u = 0; u < 4; u++)
#pragma unroll
                    for (int j = 0; j < 4; j++) S[rg][u][j] = 0.f;

#pragma unroll
            for (int s = 0; s < 8; s++) {
#pragma unroll
                for (int kb = 0; kb < 2; kb++) {
                    uint32_t b[4];
                    LDSM_X4(b[0], b[1], b[2], b[3],
                            kB + (c * 2 + kb) * 16 * A_KSTR * 2 + s * 32);
                    MMA_F16(S[0][kb * 2],     Qf[0][s][0], Qf[0][s][1], Qf[0][s][2], Qf[0][s][3], b[0], b[1]);
                    MMA_F16(S[0][kb * 2 + 1], Qf[0][s][0], Qf[0][s][1], Qf[0][s][2], Qf[0][s][3], b[2], b[3]);
                    MMA_F16(S[1][kb * 2],     Qf[1][s][0], Qf[1][s][1], Qf[1][s][2], Qf[1][s][3], b[0], b[1]);
                    MMA_F16(S[1][kb * 2 + 1], Qf[1][s][0], Qf[1][s][1], Qf[1][s][2], Qf[1][s][3], b[2], b[3]);
                }
            }

            uint32_t Af[2][2][4];
#pragma unroll
            for (int rg = 0; rg < 2; rg++) {
#pragma unroll
                for (int u = 0; u < 4; u++) {
                    float p0 = __expf(S[rg][u][0]);
                    float p1 = __expf(S[rg][u][1]);
                    float p2 = __expf(S[rg][u][2]);
                    float p3 = __expf(S[rg][u][3]);
                    lr[rg][0] += p0 + p1;
                    lr[rg][1] += p2 + p3;
                    Af[rg][u >> 1][(u & 1) * 2]     = packh2(p0, p1);
                    Af[rg][u >> 1][(u & 1) * 2 + 1] = packh2(p2, p3);
                }
            }

#pragma unroll
            for (int ks = 0; ks < 2; ks++) {
#pragma unroll
                for (int db = 0; db < 8; db++) {
                    uint32_t b[4];
                    LDSM_X4_T(b[0], b[1], b[2], b[3],
                              vB + (c * 2 + ks) * 16 * A_KSTR * 2 + db * 32);
                    MMA_F16(O[0][db * 2],     Af[0][ks][0], Af[0][ks][1], Af[0][ks][2], Af[0][ks][3], b[0], b[1]);
                    MMA_F16(O[0][db * 2 + 1], Af[0][ks][0], Af[0][ks][1], Af[0][ks][2], Af[0][ks][3], b[2], b[3]);
                    MMA_F16(O[1][db * 2],     Af[1][ks][0], Af[1][ks][1], Af[1][ks][2], Af[1][ks][3], b[0], b[1]);
                    MMA_F16(O[1][db * 2 + 1], Af[1][ks][0], Af[1][ks][1], Af[1][ks][2], Af[1][ks][3], b[2], b[3]);
                }
            }
        }
    }

#pragma unroll
    for (int rg = 0; rg < 2; rg++) {
        float l0 = lr[rg][0], l1 = lr[rg][1];
        l0 += __shfl_xor_sync(0xffffffffu, l0, 1);
        l0 += __shfl_xor_sync(0xffffffffu, l0, 2);
        l1 += __shfl_xor_sync(0xffffffffu, l1, 1);
        l1 += __shfl_xor_sync(0xffffffffu, l1, 2);
        const float inv0 = 1.0f / l0;
        const float inv1 = 1.0f / l1;
        const int r0 = m0 + base + rg * 16 + gid;
        float* o0 = &out[((size_t)(bb * L_SEQ + r0)) * E_DIM + h * HD];
        float* o1 = &out[((size_t)(bb * L_SEQ + r0 + 8)) * E_DIM + h * HD];
#pragma unroll
        for (int ud = 0; ud < 16; ud++) {
            int col = ud * 8 + tig * 2;
            *(float2*)&o0[col] = make_float2(O[rg][ud][0] * inv0, O[rg][ud][1] * inv0);
            *(float2*)&o1[col] = make_float2(O[rg][ud][2] * inv1, O[rg][ud][3] * inv1);
        }
    }
}

// ===========================================================================
extern "C" void kernel_launch(void* const* d_in, const int* in_sizes, int n_in,
                              void* d_out, int out_size)
{
    (void)in_sizes; (void)n_in; (void)out_size;
    const float* x = (const float*)d_in[0];
    const float* W = (const float*)d_in[1];
    const float* b = (const float*)d_in[2];
    float* out = (float*)d_out;

    __half* xh; cudaGetSymbolAddress((void**)&xh, g_xh);
    __half* wh; cudaGetSymbolAddress((void**)&wh, g_wh);

    // One-time stream/event creation (first call is the uncaptured
    // correctness run, so creation happens outside graph capture).
    static cudaStream_t sG = nullptr, sA = nullptr;
    static cudaEvent_t evFork, evG[B_SZ], evJoin;
    if (sG == nullptr) {
        cudaStreamCreateWithFlags(&sG, cudaStreamNonBlocking);
        cudaStreamCreateWithFlags(&sA, cudaStreamNonBlocking);
        cudaEventCreateWithFlags(&evFork, cudaEventDisableTiming);
        cudaEventCreateWithFlags(&evJoin, cudaEventDisableTiming);
        for (int i = 0; i < B_SZ; i++)
            cudaEventCreateWithFlags(&evG[i], cudaEventDisableTiming);
    }

    cudaFuncSetAttribute(qkv_gemm_b,
                         cudaFuncAttributeMaxDynamicSharedMemorySize, G_SMEM_BYTES);
    cudaFuncSetAttribute(attn_b,
                         cudaFuncAttributeMaxDynamicSharedMemorySize, A_SMEM_BYTES);

    // ---- fork from caller stream ----
    cudaEventRecord(evFork, 0);
    cudaStreamWaitEvent(sG, evFork, 0);
    cudaStreamWaitEvent(sA, evFork, 0);

    // prerounds in the GEMM stream (GEMM depends on them)
    int nx4 = (M_TOTAL * K_DIM) / 4;
    int nw4 = (N_TOTAL * K_DIM) / 4;
    to_half_kernel<<<(nx4 + 255) / 256, 256, 0, sG>>>(x, xh, nx4);
    to_half_kernel<<<(nw4 + 255) / 256, 256, 0, sG>>>(W, wh, nw4);

    // ---- pipelined per-batch GEMM -> attention ----
    for (int bb = 0; bb < B_SZ; bb++) {
        qkv_gemm_b<<<dim3(N_TOTAL / 128, L_SEQ / 128), 256, G_SMEM_BYTES, sG>>>(bb, b);
        cudaEventRecord(evG[bb], sG);
        cudaStreamWaitEvent(sA, evG[bb], 0);
        attn_b<<<dim3(L_SEQ / 128, NH), 128, A_SMEM_BYTES, sA>>>(bb, out);
    }

    // ---- join back to caller stream ----
    cudaEventRecord(evJoin, sA);
    cudaStreamWaitEvent(0, evJoin, 0);
    // sG's tail (last GEMM) is already ordered before sA's last attn via evG.
}

// round 16
// speedup vs baseline: 1.7156x; 1.7156x over previous
#include <cuda_runtime.h>
#include <cuda_fp16.h>
#include <math.h>
#include <stdint.h>

#define B_SZ   4
#define L_SEQ  2048
#define E_DIM  2048
#define NH     16
#define HD     128
#define M_TOTAL (B_SZ * L_SEQ)   /* 8192 */
#define K_DIM   E_DIM            /* 2048 */
#define N_TOTAL (3 * E_DIM)      /* 6144 */
#define BH     (B_SZ * NH)       /* 64 */

// Scratch: fp16 x, W; split q/k/v head-major buffers [bh][L][HD].
__device__ __half g_xh[(size_t)M_TOTAL * (size_t)K_DIM];
__device__ __half g_wh[(size_t)N_TOTAL * (size_t)K_DIM];
__device__ __half g_qh[(size_t)BH * L_SEQ * HD];
__device__ __half g_kh[(size_t)BH * L_SEQ * HD];
__device__ __half g_vh[(size_t)BH * L_SEQ * HD];

// ---------------------------------------------------------------------------
__device__ __forceinline__ uint32_t smem_u32(const void* p) {
    uint32_t a;
    asm("{ .reg .u64 t; cvta.to.shared.u64 t, %1; cvt.u32.u64 %0, t; }"
        : "=r"(a) : "l"(p));
    return a;
}

// packed 2^x on two log2-scaled fp32 inputs -> half2 bits
__device__ __forceinline__ uint32_t ex2_h2(float a, float b) {
    __half2 h = __floats2half2_rn(a, b);
    uint32_t x = *(uint32_t*)&h, r;
    asm("ex2.approx.f16x2 %0, %1;" : "=r"(r) : "r"(x));
    return r;
}

#define MMA_F16(c, a0, a1, a2, a3, b0, b1)                                    \
    asm volatile(                                                             \
        "mma.sync.aligned.m16n8k16.row.col.f32.f16.f16.f32 "                  \
        "{%0,%1,%2,%3}, {%4,%5,%6,%7}, {%8,%9}, {%0,%1,%2,%3};"               \
        : "+f"((c)[0]), "+f"((c)[1]), "+f"((c)[2]), "+f"((c)[3])              \
        : "r"(a0), "r"(a1), "r"(a2), "r"(a3), "r"(b0), "r"(b1))

#define LDSM_X4(r0, r1, r2, r3, addr)                                         \
    asm volatile("ldmatrix.sync.aligned.m8n8.x4.shared.b16 "                  \
                 "{%0,%1,%2,%3}, [%4];"                                       \
                 : "=r"(r0), "=r"(r1), "=r"(r2), "=r"(r3) : "r"(addr))

#define LDSM_X4_T(r0, r1, r2, r3, addr)                                       \
    asm volatile("ldmatrix.sync.aligned.m8n8.x4.trans.shared.b16 "            \
                 "{%0,%1,%2,%3}, [%4];"                                       \
                 : "=r"(r0), "=r"(r1), "=r"(r2), "=r"(r3) : "r"(addr))

#define CP_ASYNC16(dst, src)                                                  \
    asm volatile("cp.async.cg.shared.global [%0], [%1], 16;"                  \
                 :: "r"(dst), "l"(src))
#define CP_COMMIT() asm volatile("cp.async.commit_group;" ::: "memory")
#define CP_WAIT(n)  asm volatile("cp.async.wait_group %0;" :: "n"(n) : "memory")

// ===========================================================================
// Kernel 0: fp32 -> fp16 conversion
// ===========================================================================
__global__ __launch_bounds__(256) void to_half_kernel(
    const float* __restrict__ src, __half* __restrict__ dst, int n4)
{
    int i = blockIdx.x * blockDim.x + threadIdx.x;
    if (i >= n4) return;
    float4 v = ((const float4*)src)[i];
    __half2 h0 = __floats2half2_rn(v.x, v.y);
    __half2 h1 = __floats2half2_rn(v.z, v.w);
    ((uint2*)dst)[i] = make_uint2(*(uint32_t*)&h0, *(uint32_t*)&h1);
}

// ===========================================================================
// Kernel 1: QKV GEMM (R11 champion, unchanged). CTA 128x128, BK=64 halves,
// 3-stage cp.async, 8 warps 4(M)x2(N) => warp tile 32x64, 2 CTAs/SM.
// Fused bias + L2-norm epilogue -> head-major g_qh/g_kh/g_vh (fp16).
// ===========================================================================
#define GSTR 72
#define G_STAGE_H (2 * 128 * GSTR)
#define G_SMEM_BYTES (3 * G_STAGE_H * 2)   /* 110592 B */

__global__ __launch_bounds__(256, 2) void qkv_gemm_v5(
    const float* __restrict__ bias)
{
    extern __shared__ __align__(16) __half gsh[];
    const uint32_t sbase = smem_u32(gsh);
    float* red = (float*)gsh;

    const int tid  = threadIdx.x;
    const int lane = tid & 31;
    const int wid  = tid >> 5;
    const int gid  = lane >> 2;
    const int tig  = lane & 3;
    const int wm   = wid & 3;
    const int wn   = wid >> 2;
    const int m0   = blockIdx.y * 128;
    const int n0   = blockIdx.x * 128;

    const uint32_t a_lm = (uint32_t)(((lane & 15) * GSTR + (lane >> 4) * 8) * 2);
    const uint32_t b_lm = (uint32_t)(((((lane & 7) + ((lane >> 4) & 1) * 8) * GSTR)
                                      + ((lane >> 3) & 1) * 8) * 2);
    const int cp_r = tid >> 3;
    const int cp_c = tid & 7;

    float C[2][8][4];
#pragma unroll
    for (int t = 0; t < 2; t++)
#pragma unroll
        for (int u = 0; u < 8; u++)
#pragma unroll
            for (int j = 0; j < 4; j++) C[t][u][j] = 0.f;

    const int NIT = K_DIM / 64;

    auto stage_load = [&](int it, int st) {
        const int k0 = it * 64;
        const uint32_t sb = sbase + (uint32_t)(st * G_STAGE_H * 2);
#pragma unroll
        for (int i = 0; i < 4; i++) {
            int r = i * 32 + cp_r;
            uint32_t dst = sb + (uint32_t)((r * GSTR + cp_c * 8) * 2);
            const __half* src = g_xh + (size_t)(m0 + r) * K_DIM + k0 + cp_c * 8;
            CP_ASYNC16(dst, src);
        }
#pragma unroll
        for (int i = 0; i < 4; i++) {
            int r = i * 32 + cp_r;
            uint32_t dst = sb + (uint32_t)(((128 + r) * GSTR + cp_c * 8) * 2);
            const __half* src = g_wh + (size_t)(n0 + r) * K_DIM + k0 + cp_c * 8;
            CP_ASYNC16(dst, src);
        }
    };

    stage_load(0, 0); CP_COMMIT();
    stage_load(1, 1); CP_COMMIT();

    for (int it = 0; it < NIT; ++it) {
        CP_WAIT(1);
        __syncthreads();
        if (it + 2 < NIT) stage_load(it + 2, (it + 2) % 3);
        CP_COMMIT();

        const uint32_t sb = sbase + (uint32_t)(((it % 3) * G_STAGE_H) * 2);
        const uint32_t aB = sb + (uint32_t)(wm * 32 * GSTR * 2) + a_lm;
        const uint32_t bB = sb + (uint32_t)((128 + wn * 64) * GSTR * 2) + b_lm;

#pragma unroll
        for (int s = 0; s < 4; s++) {
            uint32_t a0[4], a1[4];
            LDSM_X4(a0[0], a0[1], a0[2], a0[3], aB + s * 32);
            LDSM_X4(a1[0], a1[1], a1[2], a1[3], aB + 16 * GSTR * 2 + s * 32);
#pragma unroll
            for (int up = 0; up < 4; up++) {
                uint32_t b[4];
                LDSM_X4(b[0], b[1], b[2], b[3],
                        bB + up * 16 * GSTR * 2 + s * 32);
                MMA_F16(C[0][up * 2],     a0[0], a0[1], a0[2], a0[3], b[0], b[1]);
                MMA_F16(C[0][up * 2 + 1], a0[0], a0[1], a0[2], a0[3], b[2], b[3]);
                MMA_F16(C[1][up * 2],     a1[0], a1[1], a1[2], a1[3], b[0], b[1]);
                MMA_F16(C[1][up * 2 + 1], a1[0], a1[1], a1[2], a1[3], b[2], b[3]);
            }
        }
    }

    // ---------------- fused epilogue ----------------
    CP_WAIT(0);
    __syncthreads();
    const int head = blockIdx.x / 3;
    const int comp = blockIdx.x % 3;
    const int bb   = m0 >> 11;
    const int bh   = bb * NH + head;
    __half* dstbuf = (comp == 0) ? g_qh : (comp == 1) ? g_kh : g_vh;

#pragma unroll
    for (int t = 0; t < 2; t++)
#pragma unroll
        for (int u = 0; u < 8; u++) {
            int col = n0 + wn * 64 + u * 8 + tig * 2;
            float2 bv = *(const float2*)&bias[col];
            C[t][u][0] += bv.x; C[t][u][1] += bv.y;
            C[t][u][2] += bv.x; C[t][u][3] += bv.y;
        }

    float sc[2][2] = {{1.f, 1.f}, {1.f, 1.f}};
    if (comp < 2) {
#pragma unroll
        for (int t = 0; t < 2; t++)
#pragma unroll
            for (int hh = 0; hh < 2; hh++) {
                float p = 0.f;
#pragma unroll
                for (int u = 0; u < 8; u++)
                    p += C[t][u][2 * hh] * C[t][u][2 * hh]
                       + C[t][u][2 * hh + 1] * C[t][u][2 * hh + 1];
                p += __shfl_xor_sync(0xffffffffu, p, 1);
                p += __shfl_xor_sync(0xffffffffu, p, 2);
                if (tig == 0)
                    red[(wm * 32 + t * 16 + hh * 8 + gid) * 2 + wn] = p;
            }
        __syncthreads();
#pragma unroll
        for (int t = 0; t < 2; t++)
#pragma unroll
            for (int hh = 0; hh < 2; hh++) {
                int r = wm * 32 + t * 16 + hh * 8 + gid;
                float s = red[r * 2] + red[r * 2 + 1];
                sc[t][hh] = 1.0f / fmaxf(sqrtf(s), 1e-12f);
            }
    }

#pragma unroll
    for (int t = 0; t < 2; t++) {
        int r0 = wm * 32 + t * 16 + gid;
        int l0 = (m0 + r0) & (L_SEQ - 1);
#pragma unroll
        for (int u = 0; u < 8; u++) {
            int chd = wn * 64 + u * 8 + tig * 2;
            __half2 h0 = __floats2half2_rn(C[t][u][0] * sc[t][0],
                                           C[t][u][1] * sc[t][0]);
            __half2 h1 = __floats2half2_rn(C[t][u][2] * sc[t][1],
                                           C[t][u][3] * sc[t][1]);
            *(__half2*)&dstbuf[((size_t)bh * L_SEQ + l0) * HD + chd]     = h0;
            *(__half2*)&dstbuf[((size_t)bh * L_SEQ + l0 + 8) * HD + chd] = h1;
        }
    }
}

// ===========================================================================
// Kernel 2: attention. BM=128, 4 warps x 32 rows, 2 CTAs/SM; P in registers.
// exp via packed ex2.approx.f16x2 (half the MUFU ops); l from the SAME
// rounded half P values (HADD2 pairs -> fp32), preserving softmax consistency.
// ===========================================================================
#define A_KSTR 136
#define A_KOFF(buf) ((buf) * (64 * A_KSTR))
#define A_VOFF(buf) (2 * 64 * A_KSTR + (buf) * (64 * A_KSTR))
#define A_SMEM_BYTES (4 * 64 * A_KSTR * 2)   /* 69632 B */
#define LOG2E 1.4426950408889634f

__global__ __launch_bounds__(128, 2) void attn_v8(float* __restrict__ out)
{
    extern __shared__ __align__(16) __half smh[];
    const uint32_t sbase = smem_u32(smh);

    const int tid  = threadIdx.x;
    const int lane = tid & 31;
    const int wid  = tid >> 5;
    const int gid  = lane >> 2;
    const int tig  = lane & 3;
    const int base = wid * 32;
    const int m0   = blockIdx.x * 128;
    const int bh   = blockIdx.y;
    const int bb   = bh >> 4;
    const int h    = bh & 15;
    const __half* qrow = g_qh + (size_t)bh * L_SEQ * HD;
    const __half* krow = g_kh + (size_t)bh * L_SEQ * HD;
    const __half* vrow = g_vh + (size_t)bh * L_SEQ * HD;

    uint32_t Qf[2][8][4];
#pragma unroll
    for (int rg = 0; rg < 2; rg++) {
        const __half* rq  = qrow + (size_t)(m0 + base + rg * 16 + gid) * HD;
        const __half* rq8 = rq + (size_t)8 * HD;
#pragma unroll
        for (int s = 0; s < 8; s++) {
            int c = s * 16 + tig * 2;
            Qf[rg][s][0] = *(const uint32_t*)&rq [c];
            Qf[rg][s][1] = *(const uint32_t*)&rq8[c];
            Qf[rg][s][2] = *(const uint32_t*)&rq [c + 8];
            Qf[rg][s][3] = *(const uint32_t*)&rq8[c + 8];
        }
    }

    const uint32_t k_lm = (uint32_t)(((((lane & 7) + ((lane >> 4) & 1) * 8) * A_KSTR)
                                      + ((lane >> 3) & 1) * 8) * 2);
    const uint32_t v_lm = (uint32_t)(((((lane & 7) + ((lane >> 3) & 1) * 8) * A_KSTR)
                                      + (lane >> 4) * 8) * 2);

    const int cp_r = tid >> 4;    // 0..7
    const int cp_c = tid & 15;    // 0..15

    auto stage_load = [&](int tt, int buf) {
        const int n0t = tt * 64;
#pragma unroll
        for (int i = 0; i < 8; i++) {
            int r = i * 8 + cp_r;
            uint32_t dst = sbase + (uint32_t)((A_KOFF(buf) + r * A_KSTR + cp_c * 8) * 2);
            CP_ASYNC16(dst, krow + (size_t)(n0t + r) * HD + cp_c * 8);
        }
#pragma unroll
        for (int i = 0; i < 8; i++) {
            int r = i * 8 + cp_r;
            uint32_t dst = sbase + (uint32_t)((A_VOFF(buf) + r * A_KSTR + cp_c * 8) * 2);
            CP_ASYNC16(dst, vrow + (size_t)(n0t + r) * HD + cp_c * 8);
        }
    };

    float O[2][16][4];
#pragma unroll
    for (int rg = 0; rg < 2; rg++)
#pragma unroll
        for (int u = 0; u < 16; u++)
#pragma unroll
            for (int j = 0; j < 4; j++) O[rg][u][j] = 0.f;
    float lr[2][2] = {{0.f, 0.f}, {0.f, 0.f}};

    stage_load(0, 0); CP_COMMIT();

    for (int tt = 0; tt < L_SEQ / 64; ++tt) {
        CP_WAIT(0);
        __syncthreads();
        if (tt + 1 < L_SEQ / 64) stage_load(tt + 1, (tt + 1) & 1);
        CP_COMMIT();

        const int buf = tt & 1;
        const uint32_t kB = sbase + (uint32_t)(A_KOFF(buf) * 2) + k_lm;
        const uint32_t vB = sbase + (uint32_t)(A_VOFF(buf) * 2) + v_lm;

#pragma unroll
        for (int c = 0; c < 2; c++) {
            float S[2][4][4];
#pragma unroll
            for (int rg = 0; rg < 2; rg++)
#pragma unroll
                for (int u = 0; u < 4; u++)
#pragma unroll
                    for (int j = 0; j < 4; j++) S[rg][u][j] = 0.f;

#pragma unroll
            for (int s = 0; s < 8; s++) {
#pragma unroll
                for (int kb = 0; kb < 2; kb++) {
                    uint32_t b[4];
                    LDSM_X4(b[0], b[1], b[2], b[3],
                            kB + (c * 2 + kb) * 16 * A_KSTR * 2 + s * 32);
                    MMA_F16(S[0][kb * 2],     Qf[0][s][0], Qf[0][s][1], Qf[0][s][2], Qf[0][s][3], b[0], b[1]);
                    MMA_F16(S[0][kb * 2 + 1], Qf[0][s][0], Qf[0][s][1], Qf[0][s][2], Qf[0][s][3], b[2], b[3]);
                    MMA_F16(S[1][kb * 2],     Qf[1][s][0], Qf[1][s][1], Qf[1][s][2], Qf[1][s][3], b[0], b[1]);
                    MMA_F16(S[1][kb * 2 + 1], Qf[1][s][0], Qf[1][s][1], Qf[1][s][2], Qf[1][s][3], b[2], b[3]);
                }
            }

            // ---- exp via packed ex2.approx.f16x2; Af = P half2 fragments ----
            uint32_t Af[2][2][4];
#pragma unroll
            for (int rg = 0; rg < 2; rg++) {
#pragma unroll
                for (int u = 0; u < 4; u++) {
                    Af[rg][u >> 1][(u & 1) * 2] =
                        ex2_h2(S[rg][u][0] * LOG2E, S[rg][u][1] * LOG2E);
                    Af[rg][u >> 1][(u & 1) * 2 + 1] =
                        ex2_h2(S[rg][u][2] * LOG2E, S[rg][u][3] * LOG2E);
                }
                // l accumulation from the same rounded half P values
                __half2 e0 = *(__half2*)&Af[rg][0][0];
                __half2 e1 = *(__half2*)&Af[rg][0][2];
                __half2 e2 = *(__half2*)&Af[rg][1][0];
                __half2 e3 = *(__half2*)&Af[rg][1][2];
                __half2 s01 = __hadd2(e0, e1);
                __half2 s23 = __hadd2(e2, e3);
                float2 f01 = __half22float2(s01);
                float2 f23 = __half22float2(s23);
                lr[rg][0] += (f01.x + f01.y) + (f23.x + f23.y);

                __half2 o0 = *(__half2*)&Af[rg][0][1];
                __half2 o1 = *(__half2*)&Af[rg][0][3];
                __half2 o2 = *(__half2*)&Af[rg][1][1];
                __half2 o3 = *(__half2*)&Af[rg][1][3];
                __half2 t01 = __hadd2(o0, o1);
                __half2 t23 = __hadd2(o2, o3);
                float2 g01 = __half22float2(t01);
                float2 g23 = __half22float2(t23);
                lr[rg][1] += (g01.x + g01.y) + (g23.x + g23.y);
            }

#pragma unroll
            for (int ks = 0; ks < 2; ks++) {
#pragma unroll
                for (int db = 0; db < 8; db++) {
                    uint32_t b[4];
                    LDSM_X4_T(b[0], b[1], b[2], b[3],
                              vB + (c * 2 + ks) * 16 * A_KSTR * 2 + db * 32);
                    MMA_F16(O[0][db * 2],     Af[0][ks][0], Af[0][ks][1], Af[0][ks][2], Af[0][ks][3], b[0], b[1]);
                    MMA_F16(O[0][db * 2 + 1], Af[0][ks][0], Af[0][ks][1], Af[0][ks][2], Af[0][ks][3], b[2], b[3]);
                    MMA_F16(O[1][db * 2],     Af[1][ks][0], Af[1][ks][1], Af[1][ks][2], Af[1][ks][3], b[0], b[1]);
                    MMA_F16(O[1][db * 2 + 1], Af[1][ks][0], Af[1][ks][1], Af[1][ks][2], Af[1][ks][3], b[2], b[3]);
                }
            }
        }
    }

#pragma unroll
    for (int rg = 0; rg < 2; rg++) {
        float l0 = lr[rg][0], l1 = lr[rg][1];
        l0 += __shfl_xor_sync(0xffffffffu, l0, 1);
        l0 += __shfl_xor_sync(0xffffffffu, l0, 2);
        l1 += __shfl_xor_sync(0xffffffffu, l1, 1);
        l1 += __shfl_xor_sync(0xffffffffu, l1, 2);
        const float inv0 = 1.0f / l0;
        const float inv1 = 1.0f / l1;
        const int r0 = m0 + base + rg * 16 + gid;
        float* o0 = &out[((size_t)(bb * L_SEQ + r0)) * E_DIM + h * HD];
        float* o1 = &out[((size_t)(bb * L_SEQ + r0 + 8)) * E_DIM + h * HD];
#pragma unroll
        for (int ud = 0; ud < 16; ud++) {
            int col = ud * 8 + tig * 2;
            *(float2*)&o0[col] = make_float2(O[rg][ud][0] * inv0, O[rg][ud][1] * inv0);
            *(float2*)&o1[col] = make_float2(O[rg][ud][2] * inv1, O[rg][ud][3] * inv1);
        }
    }
}

// ===========================================================================
extern "C" void kernel_launch(void* const* d_in, const int* in_sizes, int n_in,
                              void* d_out, int out_size)
{
    (void)in_sizes; (void)n_in; (void)out_size;
    const float* x = (const float*)d_in[0];
    const float* W = (const float*)d_in[1];
    const float* b = (const float*)d_in[2];
    float* out = (float*)d_out;

    __half* xh; cudaGetSymbolAddress((void**)&xh, g_xh);
    __half* wh; cudaGetSymbolAddress((void**)&wh, g_wh);

    int nx4 = (M_TOTAL * K_DIM) / 4;
    int nw4 = (N_TOTAL * K_DIM) / 4;
    to_half_kernel<<<(nx4 + 255) / 256, 256>>>(x, xh, nx4);
    to_half_kernel<<<(nw4 + 255) / 256, 256>>>(W, wh, nw4);

    cudaFuncSetAttribute(qkv_gemm_v5,
                         cudaFuncAttributeMaxDynamicSharedMemorySize, G_SMEM_BYTES);
    qkv_gemm_v5<<<dim3(N_TOTAL / 128, M_TOTAL / 128), 256, G_SMEM_BYTES>>>(b);

    cudaFuncSetAttribute(attn_v8,
                         cudaFuncAttributeMaxDynamicSharedMemorySize, A_SMEM_BYTES);
    attn_v8<<<dim3(L_SEQ / 128, BH), 128, A_SMEM_BYTES>>>(out);
}

// round 17
// speedup vs baseline: 1.7262x; 1.0062x over previous
#include <cuda_runtime.h>
#include <cuda_fp16.h>
#include <math.h>
#include <stdint.h>

#define B_SZ   4
#define L_SEQ  2048
#define E_DIM  2048
#define NH     16
#define HD     128
#define M_TOTAL (B_SZ * L_SEQ)   /* 8192 */
#define K_DIM   E_DIM            /* 2048 */
#define N_TOTAL (3 * E_DIM)      /* 6144 */
#define BH     (B_SZ * NH)       /* 64 */
#define LOG2E  1.4426950408889634f

// Scratch: fp16 x, W; split q/k/v head-major buffers [bh][L][HD].
// NOTE: q is stored pre-scaled by log2e (folded into its L2-norm scale).
__device__ __half g_xh[(size_t)M_TOTAL * (size_t)K_DIM];
__device__ __half g_wh[(size_t)N_TOTAL * (size_t)K_DIM];
__device__ __half g_qh[(size_t)BH * L_SEQ * HD];
__device__ __half g_kh[(size_t)BH * L_SEQ * HD];
__device__ __half g_vh[(size_t)BH * L_SEQ * HD];

// ---------------------------------------------------------------------------
__device__ __forceinline__ uint32_t smem_u32(const void* p) {
    uint32_t a;
    asm("{ .reg .u64 t; cvta.to.shared.u64 t, %1; cvt.u32.u64 %0, t; }"
        : "=r"(a) : "l"(p));
    return a;
}

// packed 2^x on two fp32 inputs (already log2-scaled) -> half2 bits
__device__ __forceinline__ uint32_t ex2_h2(float a, float b) {
    __half2 h = __floats2half2_rn(a, b);
    uint32_t x = *(uint32_t*)&h, r;
    asm("ex2.approx.f16x2 %0, %1;" : "=r"(r) : "r"(x));
    return r;
}

#define MMA_F16(c, a0, a1, a2, a3, b0, b1)                                    \
    asm volatile(                                                             \
        "mma.sync.aligned.m16n8k16.row.col.f32.f16.f16.f32 "                  \
        "{%0,%1,%2,%3}, {%4,%5,%6,%7}, {%8,%9}, {%0,%1,%2,%3};"               \
        : "+f"((c)[0]), "+f"((c)[1]), "+f"((c)[2]), "+f"((c)[3])              \
        : "r"(a0), "r"(a1), "r"(a2), "r"(a3), "r"(b0), "r"(b1))

#define LDSM_X4(r0, r1, r2, r3, addr)                                         \
    asm volatile("ldmatrix.sync.aligned.m8n8.x4.shared.b16 "                  \
                 "{%0,%1,%2,%3}, [%4];"                                       \
                 : "=r"(r0), "=r"(r1), "=r"(r2), "=r"(r3) : "r"(addr))

#define LDSM_X4_T(r0, r1, r2, r3, addr)                                       \
    asm volatile("ldmatrix.sync.aligned.m8n8.x4.trans.shared.b16 "            \
                 "{%0,%1,%2,%3}, [%4];"                                       \
                 : "=r"(r0), "=r"(r1), "=r"(r2), "=r"(r3) : "r"(addr))

#define CP_ASYNC16(dst, src)                                                  \
    asm volatile("cp.async.cg.shared.global [%0], [%1], 16;"                  \
                 :: "r"(dst), "l"(src))
#define CP_COMMIT() asm volatile("cp.async.commit_group;" ::: "memory")
#define CP_WAIT(n)  asm volatile("cp.async.wait_group %0;" :: "n"(n) : "memory")

// ===========================================================================
// Kernel 0: fp32 -> fp16 conversion
// ===========================================================================
__global__ __launch_bounds__(256) void to_half_kernel(
    const float* __restrict__ src, __half* __restrict__ dst, int n4)
{
    int i = blockIdx.x * blockDim.x + threadIdx.x;
    if (i >= n4) return;
    float4 v = ((const float4*)src)[i];
    __half2 h0 = __floats2half2_rn(v.x, v.y);
    __half2 h1 = __floats2half2_rn(v.z, v.w);
    ((uint2*)dst)[i] = make_uint2(*(uint32_t*)&h0, *(uint32_t*)&h1);
}

// ===========================================================================
// Kernel 1: QKV GEMM (R11 config). CTA 128x128, BK=64 halves, 3-stage
// cp.async, 8 warps 4(M)x2(N), 2 CTAs/SM. Fused bias + L2-norm epilogue;
// q additionally scaled by log2e (folded into softmax exp).
// ===========================================================================
#define GSTR 72
#define G_STAGE_H (2 * 128 * GSTR)
#define G_SMEM_BYTES (3 * G_STAGE_H * 2)   /* 110592 B */

__global__ __launch_bounds__(256, 2) void qkv_gemm_v9(
    const float* __restrict__ bias)
{
    extern __shared__ __align__(16) __half gsh[];
    const uint32_t sbase = smem_u32(gsh);
    float* red = (float*)gsh;

    const int tid  = threadIdx.x;
    const int lane = tid & 31;
    const int wid  = tid >> 5;
    const int gid  = lane >> 2;
    const int tig  = lane & 3;
    const int wm   = wid & 3;
    const int wn   = wid >> 2;
    const int m0   = blockIdx.y * 128;
    const int n0   = blockIdx.x * 128;

    const uint32_t a_lm = (uint32_t)(((lane & 15) * GSTR + (lane >> 4) * 8) * 2);
    const uint32_t b_lm = (uint32_t)(((((lane & 7) + ((lane >> 4) & 1) * 8) * GSTR)
                                      + ((lane >> 3) & 1) * 8) * 2);
    const int cp_r = tid >> 3;
    const int cp_c = tid & 7;

    float C[2][8][4];
#pragma unroll
    for (int t = 0; t < 2; t++)
#pragma unroll
        for (int u = 0; u < 8; u++)
#pragma unroll
            for (int j = 0; j < 4; j++) C[t][u][j] = 0.f;

    const int NIT = K_DIM / 64;

    auto stage_load = [&](int it, int st) {
        const int k0 = it * 64;
        const uint32_t sb = sbase + (uint32_t)(st * G_STAGE_H * 2);
#pragma unroll
        for (int i = 0; i < 4; i++) {
            int r = i * 32 + cp_r;
            uint32_t dst = sb + (uint32_t)((r * GSTR + cp_c * 8) * 2);
            const __half* src = g_xh + (size_t)(m0 + r) * K_DIM + k0 + cp_c * 8;
            CP_ASYNC16(dst, src);
        }
#pragma unroll
        for (int i = 0; i < 4; i++) {
            int r = i * 32 + cp_r;
            uint32_t dst = sb + (uint32_t)(((128 + r) * GSTR + cp_c * 8) * 2);
            const __half* src = g_wh + (size_t)(n0 + r) * K_DIM + k0 + cp_c * 8;
            CP_ASYNC16(dst, src);
        }
    };

    stage_load(0, 0); CP_COMMIT();
    stage_load(1, 1); CP_COMMIT();

    for (int it = 0; it < NIT; ++it) {
        CP_WAIT(1);
        __syncthreads();
        if (it + 2 < NIT) stage_load(it + 2, (it + 2) % 3);
        CP_COMMIT();

        const uint32_t sb = sbase + (uint32_t)(((it % 3) * G_STAGE_H) * 2);
        const uint32_t aB = sb + (uint32_t)(wm * 32 * GSTR * 2) + a_lm;
        const uint32_t bB = sb + (uint32_t)((128 + wn * 64) * GSTR * 2) + b_lm;

#pragma unroll
        for (int s = 0; s < 4; s++) {
            uint32_t a0[4], a1[4];
            LDSM_X4(a0[0], a0[1], a0[2], a0[3], aB + s * 32);
            LDSM_X4(a1[0], a1[1], a1[2], a1[3], aB + 16 * GSTR * 2 + s * 32);
#pragma unroll
            for (int up = 0; up < 4; up++) {
                uint32_t b[4];
                LDSM_X4(b[0], b[1], b[2], b[3],
                        bB + up * 16 * GSTR * 2 + s * 32);
                MMA_F16(C[0][up * 2],     a0[0], a0[1], a0[2], a0[3], b[0], b[1]);
                MMA_F16(C[0][up * 2 + 1], a0[0], a0[1], a0[2], a0[3], b[2], b[3]);
                MMA_F16(C[1][up * 2],     a1[0], a1[1], a1[2], a1[3], b[0], b[1]);
                MMA_F16(C[1][up * 2 + 1], a1[0], a1[1], a1[2], a1[3], b[2], b[3]);
            }
        }
    }

    // ---------------- fused epilogue ----------------
    CP_WAIT(0);
    __syncthreads();
    const int head = blockIdx.x / 3;
    const int comp = blockIdx.x % 3;
    const int bb   = m0 >> 11;
    const int bh   = bb * NH + head;
    __half* dstbuf = (comp == 0) ? g_qh : (comp == 1) ? g_kh : g_vh;

#pragma unroll
    for (int t = 0; t < 2; t++)
#pragma unroll
        for (int u = 0; u < 8; u++) {
            int col = n0 + wn * 64 + u * 8 + tig * 2;
            float2 bv = *(const float2*)&bias[col];
            C[t][u][0] += bv.x; C[t][u][1] += bv.y;
            C[t][u][2] += bv.x; C[t][u][3] += bv.y;
        }

    float sc[2][2] = {{1.f, 1.f}, {1.f, 1.f}};
    if (comp < 2) {
#pragma unroll
        for (int t = 0; t < 2; t++)
#pragma unroll
            for (int hh = 0; hh < 2; hh++) {
                float p = 0.f;
#pragma unroll
                for (int u = 0; u < 8; u++)
                    p += C[t][u][2 * hh] * C[t][u][2 * hh]
                       + C[t][u][2 * hh + 1] * C[t][u][2 * hh + 1];
                p += __shfl_xor_sync(0xffffffffu, p, 1);
                p += __shfl_xor_sync(0xffffffffu, p, 2);
                if (tig == 0)
                    red[(wm * 32 + t * 16 + hh * 8 + gid) * 2 + wn] = p;
            }
        __syncthreads();
        const float qs = (comp == 0) ? LOG2E : 1.0f;   // fold log2e into q
#pragma unroll
        for (int t = 0; t < 2; t++)
#pragma unroll
            for (int hh = 0; hh < 2; hh++) {
                int r = wm * 32 + t * 16 + hh * 8 + gid;
                float s = red[r * 2] + red[r * 2 + 1];
                sc[t][hh] = qs / fmaxf(sqrtf(s), 1e-12f);
            }
    }

#pragma unroll
    for (int t = 0; t < 2; t++) {
        int r0 = wm * 32 + t * 16 + gid;
        int l0 = (m0 + r0) & (L_SEQ - 1);
#pragma unroll
        for (int u = 0; u < 8; u++) {
            int chd = wn * 64 + u * 8 + tig * 2;
            __half2 h0 = __floats2half2_rn(C[t][u][0] * sc[t][0],
                                           C[t][u][1] * sc[t][0]);
            __half2 h1 = __floats2half2_rn(C[t][u][2] * sc[t][1],
                                           C[t][u][3] * sc[t][1]);
            *(__half2*)&dstbuf[((size_t)bh * L_SEQ + l0) * HD + chd]     = h0;
            *(__half2*)&dstbuf[((size_t)bh * L_SEQ + l0 + 8) * HD + chd] = h1;
        }
    }
}

// ===========================================================================
// Kernel 2: attention. BM=128, 4 warps x 32 rows, 2 CTAs/SM; P in registers.
// exp = ex2.approx.f16x2 on pre-log2-scaled scores (no FMUL);
// l = P @ ones computed by tensor MMA into a persistent C fragment
// (c0 = row sum for row gid, c2 for row gid+8 -> no shuffles).
// ===========================================================================
#define A_KSTR 136
#define A_KOFF(buf) ((buf) * (64 * A_KSTR))
#define A_VOFF(buf) (2 * 64 * A_KSTR + (buf) * (64 * A_KSTR))
#define A_SMEM_BYTES (4 * 64 * A_KSTR * 2)   /* 69632 B */
#define ONES_H2 0x3C003C00u                  /* half2(1.0, 1.0) */

__global__ __launch_bounds__(128, 2) void attn_v9(float* __restrict__ out)
{
    extern __shared__ __align__(16) __half smh[];
    const uint32_t sbase = smem_u32(smh);

    const int tid  = threadIdx.x;
    const int lane = tid & 31;
    const int wid  = tid >> 5;
    const int gid  = lane >> 2;
    const int tig  = lane & 3;
    const int base = wid * 32;
    const int m0   = blockIdx.x * 128;
    const int bh   = blockIdx.y;
    const int bb   = bh >> 4;
    const int h    = bh & 15;
    const __half* qrow = g_qh + (size_t)bh * L_SEQ * HD;
    const __half* krow = g_kh + (size_t)bh * L_SEQ * HD;
    const __half* vrow = g_vh + (size_t)bh * L_SEQ * HD;

    uint32_t Qf[2][8][4];
#pragma unroll
    for (int rg = 0; rg < 2; rg++) {
        const __half* rq  = qrow + (size_t)(m0 + base + rg * 16 + gid) * HD;
        const __half* rq8 = rq + (size_t)8 * HD;
#pragma unroll
        for (int s = 0; s < 8; s++) {
            int c = s * 16 + tig * 2;
            Qf[rg][s][0] = *(const uint32_t*)&rq [c];
            Qf[rg][s][1] = *(const uint32_t*)&rq8[c];
            Qf[rg][s][2] = *(const uint32_t*)&rq [c + 8];
            Qf[rg][s][3] = *(const uint32_t*)&rq8[c + 8];
        }
    }

    const uint32_t k_lm = (uint32_t)(((((lane & 7) + ((lane >> 4) & 1) * 8) * A_KSTR)
                                      + ((lane >> 3) & 1) * 8) * 2);
    const uint32_t v_lm = (uint32_t)(((((lane & 7) + ((lane >> 3) & 1) * 8) * A_KSTR)
                                      + (lane >> 4) * 8) * 2);

    const int cp_r = tid >> 4;    // 0..7
    const int cp_c = tid & 15;    // 0..15

    auto stage_load = [&](int tt, int buf) {
        const int n0t = tt * 64;
#pragma unroll
        for (int i = 0; i < 8; i++) {
            int r = i * 8 + cp_r;
            uint32_t dst = sbase + (uint32_t)((A_KOFF(buf) + r * A_KSTR + cp_c * 8) * 2);
            CP_ASYNC16(dst, krow + (size_t)(n0t + r) * HD + cp_c * 8);
        }
#pragma unroll
        for (int i = 0; i < 8; i++) {
            int r = i * 8 + cp_r;
            uint32_t dst = sbase + (uint32_t)((A_VOFF(buf) + r * A_KSTR + cp_c * 8) * 2);
            CP_ASYNC16(dst, vrow + (size_t)(n0t + r) * HD + cp_c * 8);
        }
    };

    float O[2][16][4];
#pragma unroll
    for (int rg = 0; rg < 2; rg++)
#pragma unroll
        for (int u = 0; u < 16; u++)
#pragma unroll
            for (int j = 0; j < 4; j++) O[rg][u][j] = 0.f;
    float lC[2][4];
#pragma unroll
    for (int rg = 0; rg < 2; rg++)
#pragma unroll
        for (int j = 0; j < 4; j++) lC[rg][j] = 0.f;

    stage_load(0, 0); CP_COMMIT();

    for (int tt = 0; tt < L_SEQ / 64; ++tt) {
        CP_WAIT(0);
        __syncthreads();
        if (tt + 1 < L_SEQ / 64) stage_load(tt + 1, (tt + 1) & 1);
        CP_COMMIT();

        const int buf = tt & 1;
        const uint32_t kB = sbase + (uint32_t)(A_KOFF(buf) * 2) + k_lm;
        const uint32_t vB = sbase + (uint32_t)(A_VOFF(buf) * 2) + v_lm;

#pragma unroll
        for (int c = 0; c < 2; c++) {
            float S[2][4][4];
#pragma unroll
            for (int rg = 0; rg < 2; rg++)
#pragma unroll
                for (int u = 0; u < 4; u++)
#pragma unroll
                    for (int j = 0; j < 4; j++) S[rg][u][j] = 0.f;

#pragma unroll
            for (int s = 0; s < 8; s++) {
#pragma unroll
                for (int kb = 0; kb < 2; kb++) {
                    uint32_t b[4];
                    LDSM_X4(b[0], b[1], b[2], b[3],
                            kB + (c * 2 + kb) * 16 * A_KSTR * 2 + s * 32);
                    MMA_F16(S[0][kb * 2],     Qf[0][s][0], Qf[0][s][1], Qf[0][s][2], Qf[0][s][3], b[0], b[1]);
                    MMA_F16(S[0][kb * 2 + 1], Qf[0][s][0], Qf[0][s][1], Qf[0][s][2], Qf[0][s][3], b[2], b[3]);
                    MMA_F16(S[1][kb * 2],     Qf[1][s][0], Qf[1][s][1], Qf[1][s][2], Qf[1][s][3], b[0], b[1]);
                    MMA_F16(S[1][kb * 2 + 1], Qf[1][s][0], Qf[1][s][1], Qf[1][s][2], Qf[1][s][3], b[2], b[3]);
                }
            }

            // ---- P = 2^S (packed ex2, no FMUL: q pre-scaled by log2e) ----
            uint32_t Af[2][2][4];
#pragma unroll
            for (int rg = 0; rg < 2; rg++) {
#pragma unroll
                for (int u = 0; u < 4; u++) {
                    Af[rg][u >> 1][(u & 1) * 2] =
                        ex2_h2(S[rg][u][0], S[rg][u][1]);
                    Af[rg][u >> 1][(u & 1) * 2 + 1] =
                        ex2_h2(S[rg][u][2], S[rg][u][3]);
                }
            }

            // ---- l += P @ ones (tensor pipe) ----
#pragma unroll
            for (int rg = 0; rg < 2; rg++)
#pragma unroll
                for (int ks = 0; ks < 2; ks++)
                    MMA_F16(lC[rg], Af[rg][ks][0], Af[rg][ks][1],
                            Af[rg][ks][2], Af[rg][ks][3], ONES_H2, ONES_H2);

            // ---- O += P . V ----
#pragma unroll
            for (int ks = 0; ks < 2; ks++) {
#pragma unroll
                for (int db = 0; db < 8; db++) {
                    uint32_t b[4];
                    LDSM_X4_T(b[0], b[1], b[2], b[3],
                              vB + (c * 2 + ks) * 16 * A_KSTR * 2 + db * 32);
                    MMA_F16(O[0][db * 2],     Af[0][ks][0], Af[0][ks][1], Af[0][ks][2], Af[0][ks][3], b[0], b[1]);
                    MMA_F16(O[0][db * 2 + 1], Af[0][ks][0], Af[0][ks][1], Af[0][ks][2], Af[0][ks][3], b[2], b[3]);
                    MMA_F16(O[1][db * 2],     Af[1][ks][0], Af[1][ks][1], Af[1][ks][2], Af[1][ks][3], b[0], b[1]);
                    MMA_F16(O[1][db * 2 + 1], Af[1][ks][0], Af[1][ks][1], Af[1][ks][2], Af[1][ks][3], b[2], b[3]);
                }
            }
        }
    }

    // ---- epilogue: l already reduced per-row in lC (c0 / c2) ----
#pragma unroll
    for (int rg = 0; rg < 2; rg++) {
        const float inv0 = 1.0f / lC[rg][0];
        const float inv1 = 1.0f / lC[rg][2];
        const int r0 = m0 + base + rg * 16 + gid;
        float* o0 = &out[((size_t)(bb * L_SEQ + r0)) * E_DIM + h * HD];
        float* o1 = &out[((size_t)(bb * L_SEQ + r0 + 8)) * E_DIM + h * HD];
#pragma unroll
        for (int ud = 0; ud < 16; ud++) {
            int col = ud * 8 + tig * 2;
            *(float2*)&o0[col] = make_float2(O[rg][ud][0] * inv0, O[rg][ud][1] * inv0);
            *(float2*)&o1[col] = make_float2(O[rg][ud][2] * inv1, O[rg][ud][3] * inv1);
        }
    }
}

// ===========================================================================
extern "C" void kernel_launch(void* const* d_in, const int* in_sizes, int n_in,
                              void* d_out, int out_size)
{
    (void)in_sizes; (void)n_in; (void)out_size;
    const float* x = (const float*)d_in[0];
    const float* W = (const float*)d_in[1];
    const float* b = (const float*)d_in[2];
    float* out = (float*)d_out;

    __half* xh; cudaGetSymbolAddress((void**)&xh, g_xh);
    __half* wh; cudaGetSymbolAddress((void**)&wh, g_wh);

    int nx4 = (M_TOTAL * K_DIM) / 4;
    int nw4 = (N_TOTAL * K_DIM) / 4;
    to_half_kernel<<<(nx4 + 255) / 256, 256>>>(x, xh, nx4);
    to_half_kernel<<<(nw4 + 255) / 256, 256>>>(W, wh, nw4);

    cudaFuncSetAttribute(qkv_gemm_v9,
                         cudaFuncAttributeMaxDynamicSharedMemorySize, G_SMEM_BYTES);
    qkv_gemm_v9<<<dim3(N_TOTAL / 128, M_TOTAL / 128), 256, G_SMEM_BYTES>>>(b);

    cudaFuncSetAttribute(attn_v9,
                         cudaFuncAttributeMaxDynamicSharedMemorySize, A_SMEM_BYTES);
    attn_v9<<<dim3(L_SEQ / 128, BH), 128, A_SMEM_BYTES>>>(out);
}